// round 3
// baseline (speedup 1.0000x reference)
#include <cuda_runtime.h>

// ---------------------------------------------------------------------------
// Deformable Conv2d (B=8, Cin=128, H=W=64, Cout=256, K=3, pad=1) + BN + SiLU
// Pipeline:
//   1) x NCHW -> NHWC transpose (gather-friendly: 512B contiguous per (y,x))
//   2) weight transposes: dconv_w -> w_t[k][cout], offset_w -> ow_t[k][18]
//      with k = tap*128 + cin
//   3) offset conv (thread-per-pixel, 18 accumulators, weights in smem)
//   4) fused bilinear-gather + GEMM: block = 32 pixels, patches in smem,
//      256 threads = 1 cout x 32 px each
//   5) BN reduce (deterministic tree) + finalize (normalize + SiLU)
// ---------------------------------------------------------------------------

constexpr int Bn   = 8;
constexpr int CIN  = 128;
constexpr int HH   = 64;
constexpr int WW   = 64;
constexpr int COUT = 256;
constexpr int KK   = 9;
constexpr int HW   = HH * WW;          // 4096
constexpr int KDIM = CIN * KK;         // 1152
constexpr int PROW = 36;               // padded patch row (32 px + 4 pad, 16B-aligned)

// Scratch (static device globals; no allocation allowed)
__device__ float g_xt[Bn * HW * CIN];            // NHWC x   (16.8 MB)
__device__ float g_wt[(KDIM + 2) * COUT];        // w_t[k][cout], 2 zero pad rows
__device__ float g_owt[KDIM * 18];               // ow_t[k][co]
__device__ float g_off[Bn * 18 * HW];            // offset conv output (NCHW)
__device__ float g_y[Bn * COUT * HW];            // deformable conv output (NCHW)
__device__ float g_mean[COUT];
__device__ float g_rstd[COUT];

// ---------------- 1) x NCHW -> NHWC ----------------
__global__ void k_transpose_x(const float* __restrict__ x) {
    __shared__ float tile[32][33];
    int b   = blockIdx.z;
    int hw0 = blockIdx.x * 32;
    int c0  = blockIdx.y * 32;
    int tx = threadIdx.x, ty = threadIdx.y;
    tile[ty][tx] = x[(b * CIN + c0 + ty) * HW + hw0 + tx];
    __syncthreads();
    g_xt[(b * HW + hw0 + ty) * CIN + c0 + tx] = tile[tx][ty];
}

// ---------------- 2) weight transposes ----------------
__global__ void k_prep_w(const float* __restrict__ dw, const float* __restrict__ ow) {
    int tid = blockIdx.x * 256 + threadIdx.x;
    if (tid < KDIM * COUT) {
        int cout = tid & (COUT - 1);
        int k    = tid >> 8;
        int tap  = k >> 7;
        int c    = k & 127;
        g_wt[k * COUT + cout] = dw[(cout * CIN + c) * KK + tap];
    } else if (tid < (KDIM + 2) * COUT) {
        g_wt[tid] = 0.0f;                       // pad rows for prefetch
    } else if (tid < (KDIM + 2) * COUT + KDIM * 18) {
        int j  = tid - (KDIM + 2) * COUT;
        int co = j % 18;
        int k  = j / 18;
        int tap = k >> 7;
        int c   = k & 127;
        g_owt[k * 18 + co] = ow[(co * CIN + c) * KK + tap];
    }
}

// ---------------- 3) offset conv ----------------
// thread = one output pixel, 18 couts in registers; weights staged in smem.
__global__ void k_offset_conv(const float* __restrict__ offset_b) {
    extern __shared__ float w_sm[];             // 1152*18 floats = 82,944 B
    int tid = threadIdx.x;
    for (int i = tid; i < KDIM * 18; i += 256) w_sm[i] = g_owt[i];
    __syncthreads();

    int pid = blockIdx.x * 256 + tid;           // 32768 pixels total
    int b   = pid >> 12;
    int rem = pid & 4095;
    int ho  = rem >> 6;
    int wo  = rem & 63;

    float acc[18];
#pragma unroll
    for (int co = 0; co < 18; ++co) acc[co] = offset_b[co];

#pragma unroll
    for (int tap = 0; tap < 9; ++tap) {
        int y = ho - 1 + tap / 3;
        int x = wo - 1 + tap % 3;
        if ((unsigned)y < 64u && (unsigned)x < 64u) {
            const float4* xp = reinterpret_cast<const float4*>(
                g_xt + (((b * 64 + y) * 64 + x) << 7));
            const float* wbase = w_sm + tap * 128 * 18;
#pragma unroll 1
            for (int c4 = 0; c4 < 32; ++c4) {
                float4 v = xp[c4];
                float vv[4] = {v.x, v.y, v.z, v.w};
#pragma unroll
                for (int j = 0; j < 4; ++j) {
                    float xv = vv[j];
                    const float2* wr = reinterpret_cast<const float2*>(
                        wbase + (c4 * 4 + j) * 18);
#pragma unroll
                    for (int q = 0; q < 9; ++q) {
                        float2 wv = wr[q];
                        acc[2 * q]     = fmaf(xv, wv.x, acc[2 * q]);
                        acc[2 * q + 1] = fmaf(xv, wv.y, acc[2 * q + 1]);
                    }
                }
            }
        }
    }
#pragma unroll
    for (int co = 0; co < 18; ++co)
        g_off[(b * 18 + co) * HW + rem] = acc[co];
}

// ---------------- 4) fused gather + GEMM ----------------
// block = (b, ho, wo0): 32 contiguous pixels. smem patches[1152][36].
// 256 threads: gather phase -> each thread = one cout, 32 px accumulators.
__global__ void k_main(const float* __restrict__ dconv_b) {
    extern __shared__ float sm[];
    float* sm_patch = sm;                                    // 1152*36
    float* sm_wy = sm + KDIM * PROW;                         // 288
    float* sm_wx = sm_wy + 288;                              // 288
    int*   sm_y0 = reinterpret_cast<int*>(sm_wx + 288);      // 288
    int*   sm_x0 = sm_y0 + 288;                              // 288

    int tid = threadIdx.x;
    int bi  = blockIdx.x;
    int b   = bi >> 7;
    int rem = bi & 127;
    int ho  = rem >> 1;
    int wo0 = (rem & 1) << 5;

    // Phase A: sampling coordinates for 9 taps x 32 pixels
    for (int i = tid; i < 288; i += 256) {
        int tap = i >> 5, p = i & 31;
        int wo = wo0 + p;
        float dy = g_off[(b * 18 + tap * 2)     * HW + ho * 64 + wo];
        float dx = g_off[(b * 18 + tap * 2 + 1) * HW + ho * 64 + wo];
        float sy = (float)(ho - 1 + tap / 3) + dy;
        float sx = (float)(wo - 1 + tap % 3) + dx;
        float fy = floorf(sy), fx = floorf(sx);
        sm_y0[i] = (int)fy;
        sm_x0[i] = (int)fx;
        sm_wy[i] = sy - fy;
        sm_wx[i] = sx - fx;
    }
    __syncthreads();

    // Phase B: bilinear gather into smem patches (warp = (pixel,tap,c-chunk))
    int warp = tid >> 5, lane = tid & 31;
    for (int t = warp; t < 1152; t += 8) {
        int pair = t >> 2;                       // (tap, p)
        int c    = ((t & 3) << 5) + lane;
        int tap  = pair >> 5, p = pair & 31;
        int y0 = sm_y0[pair], x0 = sm_x0[pair];
        float wy = sm_wy[pair], wx = sm_wx[pair];
        bool yv0 = (unsigned)y0       < 64u;
        bool yv1 = (unsigned)(y0 + 1) < 64u;
        bool xv0 = (unsigned)x0       < 64u;
        bool xv1 = (unsigned)(x0 + 1) < 64u;
        int yc0 = max(0, min(63, y0));
        int yc1 = max(0, min(63, y0 + 1));
        int xc0 = max(0, min(63, x0));
        int xc1 = max(0, min(63, x0 + 1));
        const float* xb = g_xt + (b * HW) * CIN + c;
        float v00 = (yv0 && xv0) ? xb[(yc0 * 64 + xc0) * CIN] : 0.f;
        float v01 = (yv0 && xv1) ? xb[(yc0 * 64 + xc1) * CIN] : 0.f;
        float v10 = (yv1 && xv0) ? xb[(yc1 * 64 + xc0) * CIN] : 0.f;
        float v11 = (yv1 && xv1) ? xb[(yc1 * 64 + xc1) * CIN] : 0.f;
        float val = (1.f - wy) * ((1.f - wx) * v00 + wx * v01)
                  +        wy  * ((1.f - wx) * v10 + wx * v11);
        sm_patch[(tap * 128 + c) * PROW + p] = val;
    }
    __syncthreads();

    // Phase C: GEMM. thread = cout; 32 pixel accumulators; w prefetch depth 2.
    int cout = tid;
    float acc[32];
#pragma unroll
    for (int j = 0; j < 32; ++j) acc[j] = 0.f;

    const float* wcol = g_wt + cout;
    float w0v = wcol[0];
    float w1v = wcol[COUT];
#pragma unroll 2
    for (int k = 0; k < KDIM; ++k) {
        float wp = wcol[(k + 2) * COUT];         // pad rows make this safe
        const float4* row = reinterpret_cast<const float4*>(sm_patch + k * PROW);
#pragma unroll
        for (int j = 0; j < 8; ++j) {
            float4 v = row[j];
            acc[4 * j + 0] = fmaf(w0v, v.x, acc[4 * j + 0]);
            acc[4 * j + 1] = fmaf(w0v, v.y, acc[4 * j + 1]);
            acc[4 * j + 2] = fmaf(w0v, v.z, acc[4 * j + 2]);
            acc[4 * j + 3] = fmaf(w0v, v.w, acc[4 * j + 3]);
        }
        w0v = w1v;
        w1v = wp;
    }

    float bias = dconv_b[cout];
    float4* outp = reinterpret_cast<float4*>(
        g_y + (b * COUT + cout) * HW + ho * 64 + wo0);
#pragma unroll
    for (int j = 0; j < 8; ++j) {
        float4 o;
        o.x = acc[4 * j + 0] + bias;
        o.y = acc[4 * j + 1] + bias;
        o.z = acc[4 * j + 2] + bias;
        o.w = acc[4 * j + 3] + bias;
        outp[j] = o;
    }
}

// ---------------- 5a) BN statistics (deterministic) ----------------
__global__ void k_bn_reduce() {
    int c = blockIdx.x;
    int tid = threadIdx.x;
    float s = 0.f, s2 = 0.f;
    for (int b = 0; b < Bn; ++b) {
        const float4* p = reinterpret_cast<const float4*>(g_y + (b * COUT + c) * HW);
        for (int i = tid; i < HW / 4; i += 256) {
            float4 v = p[i];
            s  += v.x + v.y + v.z + v.w;
            s2 += v.x * v.x + v.y * v.y + v.z * v.z + v.w * v.w;
        }
    }
    __shared__ float rs[256], rs2[256];
    rs[tid] = s; rs2[tid] = s2;
    __syncthreads();
    for (int o = 128; o > 0; o >>= 1) {
        if (tid < o) { rs[tid] += rs[tid + o]; rs2[tid] += rs2[tid + o]; }
        __syncthreads();
    }
    if (tid == 0) {
        float inv = 1.0f / (Bn * HW);
        float m = rs[0] * inv;
        float var = rs2[0] * inv - m * m;
        g_mean[c] = m;
        g_rstd[c] = rsqrtf(var + 1e-5f);
    }
}

// ---------------- 5b) normalize + SiLU ----------------
__global__ void k_finalize(const float* __restrict__ gamma,
                           const float* __restrict__ beta,
                           float* __restrict__ out) {
    int idx = blockIdx.x * 256 + threadIdx.x;    // float4 index, 2,097,152 total
    int c = (idx >> 10) & 255;                   // 1024 float4 per (b,c) plane
    float m = g_mean[c];
    float scale = g_rstd[c] * gamma[c];
    float shift = beta[c] - m * scale;
    float4 v = reinterpret_cast<const float4*>(g_y)[idx];
    float4 o;
    {
        float z = v.x * scale + shift; o.x = z / (1.f + __expf(-z));
    }
    {
        float z = v.y * scale + shift; o.y = z / (1.f + __expf(-z));
    }
    {
        float z = v.z * scale + shift; o.z = z / (1.f + __expf(-z));
    }
    {
        float z = v.w * scale + shift; o.w = z / (1.f + __expf(-z));
    }
    reinterpret_cast<float4*>(out)[idx] = o;
}

// ---------------------------------------------------------------------------
extern "C" void kernel_launch(void* const* d_in, const int* in_sizes, int n_in,
                              void* d_out, int out_size) {
    const float* x  = (const float*)d_in[0];
    const float* ow = (const float*)d_in[1];
    const float* ob = (const float*)d_in[2];
    const float* dw = (const float*)d_in[3];
    const float* db = (const float*)d_in[4];
    const float* ga = (const float*)d_in[5];
    const float* be = (const float*)d_in[6];
    float* out = (float*)d_out;

    cudaFuncSetAttribute(k_offset_conv,
                         cudaFuncAttributeMaxDynamicSharedMemorySize, KDIM * 18 * 4);
    cudaFuncSetAttribute(k_main,
                         cudaFuncAttributeMaxDynamicSharedMemorySize,
                         (KDIM * PROW + 288 * 4) * 4);

    k_transpose_x<<<dim3(HW / 32, CIN / 32, Bn), dim3(32, 32)>>>(x);
    k_prep_w<<<1235, 256>>>(dw, ow);                       // 316,160 work items
    k_offset_conv<<<128, 256, KDIM * 18 * 4>>>(ob);
    k_main<<<1024, 256, (KDIM * PROW + 288 * 4) * 4>>>(db);
    k_bn_reduce<<<COUT, 256>>>();
    k_finalize<<<8192, 256>>>(ga, be, out);
}